// round 13
// baseline (speedup 1.0000x reference)
#include <cuda_runtime.h>
#include <math.h>

#define B_ 32
#define S_ 512
#define M_ (B_*S_)
#define NT 256
#define NBSCAN 256

typedef unsigned long long ull;

// ---------------- packed f32x2 helpers (Blackwell FFMA2 path) --------------
__device__ __forceinline__ ull fma2(ull a, ull b, ull c) {
    ull d;
    asm("fma.rn.f32x2 %0, %1, %2, %3;" : "=l"(d) : "l"(a), "l"(b), "l"(c));
    return d;
}
__device__ __forceinline__ ull add2(ull a, ull b) {
    ull d;
    asm("add.rn.f32x2 %0, %1, %2;" : "=l"(d) : "l"(a), "l"(b));
    return d;
}
__device__ __forceinline__ ull pack2(float x) {
    ull d;
    asm("mov.b64 %0, {%1, %1};" : "=l"(d) : "f"(x));
    return d;
}
__device__ __forceinline__ float2 unpk(ull v) {
    float2 f;
    asm("mov.b64 {%0, %1}, %2;" : "=f"(f.x), "=f"(f.y) : "l"(v));
    return f;
}

// ---------------- device-global scratch (no allocations allowed) -----------
__device__ float g_xg[(size_t)M_ * 3072];
__device__ float g_y0[(size_t)M_ * 512];
__device__ float g_y1[(size_t)M_ * 1024];
__device__ float g_y2[(size_t)M_ * 512];
__device__ float g_h [B_ * 1024];
__device__ float g_rh[B_ * 1024];
// region flags: [layer][phase:h/rh][region][pad32]  (zero-initialized)
__device__ unsigned g_cnt[3 * 2 * 8 * 32];

// lane-0-only acquire poll; short spin then tiny sleep.
__device__ __forceinline__ void waitge_warp(const unsigned* p, unsigned target) {
    if ((threadIdx.x & 31) == 0) {
        unsigned v;
        int spins = 0;
        for (;;) {
            asm volatile("ld.acquire.gpu.global.u32 %0, [%1];" : "=r"(v) : "l"(p) : "memory");
            if (v >= target) break;
            if (++spins > 32) __nanosleep(64);
        }
    }
    __syncwarp();
}
__device__ __forceinline__ void arrive(unsigned* p) {
    __threadfence();
    asm volatile("red.release.gpu.global.add.u32 [%0], 1;" :: "l"(p) : "memory");
}

// ---------------- GEMM: Y[M,N] = X[M,K] @ W[N,K]^T + bias, optional relu ---
// 128x128 tile, BK=8, 256 threads, 8x8 microtile, f32x2-packed accumulators.
__global__ void __launch_bounds__(256) gemm_k(
    const float* __restrict__ X, const float* __restrict__ W,
    const float* __restrict__ bias, float* __restrict__ Y,
    int N, int K, int relu)
{
    __shared__ float Xs[8][132];
    __shared__ float Wsm[8][132];
    const int tid = threadIdx.x;
    const int tx = tid & 15, ty = tid >> 4;
    const int n0 = blockIdx.x * 128, m0 = blockIdx.y * 128;
    const int lrow = tid >> 1;
    const int lkq  = (tid & 1) * 4;

    const float* Xp = X + (size_t)(m0 + lrow) * K + lkq;
    const float* Wp = W + (size_t)(n0 + lrow) * K + lkq;

    ull acc[8][4];
#pragma unroll
    for (int i = 0; i < 8; i++)
#pragma unroll
        for (int j = 0; j < 4; j++) acc[i][j] = 0ull;

    float4 xa = __ldg((const float4*)(Xp));
    float4 wa = __ldg((const float4*)(Wp));

    for (int kt = 0; kt < K; kt += 8) {
        __syncthreads();
        Xs[lkq + 0][lrow] = xa.x;  Xs[lkq + 1][lrow] = xa.y;
        Xs[lkq + 2][lrow] = xa.z;  Xs[lkq + 3][lrow] = xa.w;
        Wsm[lkq + 0][lrow] = wa.x; Wsm[lkq + 1][lrow] = wa.y;
        Wsm[lkq + 2][lrow] = wa.z; Wsm[lkq + 3][lrow] = wa.w;
        __syncthreads();
        if (kt + 8 < K) {
            xa = __ldg((const float4*)(Xp + kt + 8));
            wa = __ldg((const float4*)(Wp + kt + 8));
        }
#pragma unroll
        for (int k = 0; k < 8; k++) {
            float4 a0 = *(const float4*)&Xs[k][ty * 8];
            float4 a1 = *(const float4*)&Xs[k][ty * 8 + 4];
            ulonglong2 blo = *(const ulonglong2*)&Wsm[k][tx * 8];
            ulonglong2 bhi = *(const ulonglong2*)&Wsm[k][tx * 8 + 4];
            ull b0 = blo.x, b1 = blo.y, b2 = bhi.x, b3 = bhi.y;
            ull A;
            A = pack2(a0.x); acc[0][0]=fma2(A,b0,acc[0][0]); acc[0][1]=fma2(A,b1,acc[0][1]); acc[0][2]=fma2(A,b2,acc[0][2]); acc[0][3]=fma2(A,b3,acc[0][3]);
            A = pack2(a0.y); acc[1][0]=fma2(A,b0,acc[1][0]); acc[1][1]=fma2(A,b1,acc[1][1]); acc[1][2]=fma2(A,b2,acc[1][2]); acc[1][3]=fma2(A,b3,acc[1][3]);
            A = pack2(a0.z); acc[2][0]=fma2(A,b0,acc[2][0]); acc[2][1]=fma2(A,b1,acc[2][1]); acc[2][2]=fma2(A,b2,acc[2][2]); acc[2][3]=fma2(A,b3,acc[2][3]);
            A = pack2(a0.w); acc[3][0]=fma2(A,b0,acc[3][0]); acc[3][1]=fma2(A,b1,acc[3][1]); acc[3][2]=fma2(A,b2,acc[3][2]); acc[3][3]=fma2(A,b3,acc[3][3]);
            A = pack2(a1.x); acc[4][0]=fma2(A,b0,acc[4][0]); acc[4][1]=fma2(A,b1,acc[4][1]); acc[4][2]=fma2(A,b2,acc[4][2]); acc[4][3]=fma2(A,b3,acc[4][3]);
            A = pack2(a1.y); acc[5][0]=fma2(A,b0,acc[5][0]); acc[5][1]=fma2(A,b1,acc[5][1]); acc[5][2]=fma2(A,b2,acc[5][2]); acc[5][3]=fma2(A,b3,acc[5][3]);
            A = pack2(a1.z); acc[6][0]=fma2(A,b0,acc[6][0]); acc[6][1]=fma2(A,b1,acc[6][1]); acc[6][2]=fma2(A,b2,acc[6][2]); acc[6][3]=fma2(A,b3,acc[6][3]);
            A = pack2(a1.w); acc[7][0]=fma2(A,b0,acc[7][0]); acc[7][1]=fma2(A,b1,acc[7][1]); acc[7][2]=fma2(A,b2,acc[7][2]); acc[7][3]=fma2(A,b3,acc[7][3]);
        }
    }

    float bv[8];
    const float* bp = bias + n0 + tx * 8;
#pragma unroll
    for (int j = 0; j < 8; j++) bv[j] = __ldg(bp + j);

#pragma unroll
    for (int i = 0; i < 8; i++) {
        float* yp = Y + (size_t)(m0 + ty * 8 + i) * N + n0 + tx * 8;
#pragma unroll
        for (int j2 = 0; j2 < 4; j2++) {
            float2 p = unpk(acc[i][j2]);
            float o0 = p.x + bv[2 * j2];
            float o1 = p.y + bv[2 * j2 + 1];
            if (relu) { o0 = fmaxf(o0, 0.0f); o1 = fmaxf(o1, 0.0f); }
            float2 o; o.x = o0; o.y = o1;
            *(float2*)(yp + 2 * j2) = o;
        }
    }
}

// ---------------- persistent GRU scan (region-flag sync, K-split warps) ----
// 256 blocks (2 CTAs/SM so flag waits of one CTA hide behind the co-resident
// CTA's compute). Block owns JB hidden cols; warp w consumes k-region w (H/8).
// Producer blocks [32R,32R+32) own exactly the cols of region R: per-region
// counters (target 32/step) give producer->consumer sync. Lane-0-only poll.
template <int H, int JB>
__global__ void __launch_bounds__(NT, 2) gru_scan(
    const float* __restrict__ xg, const float* __restrict__ Wh,
    const float* __restrict__ h0, float* __restrict__ y, int L)
{
    constexpr int VR1   = 2 * JB;        // phase-1 rows (r,z interleaved)
    constexpr int G3    = 3 * H;
    constexpr int ITERS = H / 64;        // packed-quad iters per thread
    constexpr int P1    = (VR1 * 32 + NT - 1) / NT;
    constexpr int P2    = (JB * 32 + NT - 1) / NT;

    extern __shared__ float smem[];
    float* Ws1  = smem;                          // VR1*H   r/z rows (v=2*jl+g)
    float* Ws2  = Ws1 + VR1 * H;                 // JB*H    n rows
    ull*   red  = (ull*)(Ws2 + JB * H);          // 8*VR1*32 partials
    float* hloc = (float*)(red + 8 * VR1 * 32);  // JB*32
    float* zbuf = hloc + JB * 32;                // JB*32

    const int tid  = threadIdx.x;
    const int wid  = tid >> 5;
    const int lane = tid & 31;
    const int kh   = lane >> 4;          // k-subslice within warp
    const int b16  = lane & 15;          // batch pair base
    const int j0   = blockIdx.x * JB;
    const int R    = blockIdx.x >> 5;    // my producer region (32 blocks each)

    unsigned* cnt_h  = g_cnt + ((L * 2 + 0) * 8) * 32;
    unsigned* cnt_rh = g_cnt + ((L * 2 + 1) * 8) * 32;

    // cache Wh slice in shared (reused 512 steps)
    for (int i = tid; i < VR1 * H; i += NT) {
        int v = i / H, k = i - v * H;
        int jl = v >> 1, g = v & 1;
        Ws1[i] = Wh[(size_t)(g * H + j0 + jl) * H + k];
    }
    for (int i = tid; i < JB * H; i += NT) {
        int jl = i / H, k = i - jl * H;
        Ws2[i] = Wh[(size_t)(2 * H + j0 + jl) * H + k];
    }
    // init hidden state (h0 broadcast over batch)
    for (int i = tid; i < JB * 32; i += NT) {
        int jl = i >> 5, b = i & 31;
        float v = h0[j0 + jl];
        hloc[i] = v;
        g_h[(size_t)b * H + j0 + jl] = v;
    }
    __syncthreads();
    if (tid == 0) arrive(&cnt_h[R * 32]);

    const int kbase = wid * (H / 8) + kh * 4;
    const int bA = b16, bB = b16 + 16;

    for (int t = 0; t < S_; t++) {
        const unsigned tgt = 32u * (unsigned)(t + 1);

        // -------- prefetch this step's xg values (independent of flags) ----
        float x1[P1];
#pragma unroll
        for (int pi = 0; pi < P1; pi++) {
            int o = tid + pi * NT;
            if (o < VR1 * 32) {
                int v = o >> 5, b = o & 31;
                int jl = v >> 1, g = v & 1;
                x1[pi] = __ldg(&xg[((size_t)b * S_ + t) * G3 + g * H + j0 + jl]);
            }
        }
        float x2[P2];
#pragma unroll
        for (int pi = 0; pi < P2; pi++) {
            int o = tid + pi * NT;
            if (o < JB * 32) {
                int jl = o >> 5, b = o & 31;
                x2[pi] = __ldg(&xg[((size_t)b * S_ + t) * G3 + 2 * H + j0 + jl]);
            }
        }

        // ================= phase 1: r,z over h =================
        {
            waitge_warp(&cnt_h[wid * 32], tgt);
            ull accA[VR1], accB[VR1];
#pragma unroll
            for (int v = 0; v < VR1; v++) { accA[v] = 0ull; accB[v] = 0ull; }
            const float* hAp = g_h + (size_t)bA * H + kbase;
            const float* hBp = g_h + (size_t)bB * H + kbase;
            ulonglong2 a  = __ldcg((const ulonglong2*)hAp);
            ulonglong2 b2 = __ldcg((const ulonglong2*)hBp);
#pragma unroll
            for (int i = 0; i < ITERS; i++) {
                ulonglong2 ca = a, cb = b2;
                if (i + 1 < ITERS) {
                    a  = __ldcg((const ulonglong2*)(hAp + (i + 1) * 8));
                    b2 = __ldcg((const ulonglong2*)(hBp + (i + 1) * 8));
                }
                const float* wp = Ws1 + kbase + i * 8;
#pragma unroll
                for (int v = 0; v < VR1; v++) {
                    ulonglong2 wv = *(const ulonglong2*)(wp + v * H);
                    accA[v] = fma2(ca.x, wv.x, accA[v]);
                    accA[v] = fma2(ca.y, wv.y, accA[v]);
                    accB[v] = fma2(cb.x, wv.x, accB[v]);
                    accB[v] = fma2(cb.y, wv.y, accB[v]);
                }
            }
#pragma unroll
            for (int v = 0; v < VR1; v++) {
                ull oA = add2(accA[v], __shfl_xor_sync(0xffffffffu, accA[v], 16));
                ull oB = add2(accB[v], __shfl_xor_sync(0xffffffffu, accB[v], 16));
                red[(wid * VR1 + v) * 32 + lane] = (lane < 16) ? oA : oB;
            }
            __syncthreads();
#pragma unroll
            for (int pi = 0; pi < P1; pi++) {
                int o = tid + pi * NT;
                if (o < VR1 * 32) {
                    int v = o >> 5, b = o & 31;
                    ull s = red[v * 32 + b];
#pragma unroll
                    for (int w = 1; w < 8; w++) s = add2(s, red[(w * VR1 + v) * 32 + b]);
                    float2 p = unpk(s);
                    float dot = p.x + p.y;
                    int jl = v >> 1, g = v & 1, j = j0 + jl;
                    float pre = x1[pi] + dot;
                    float sg = 1.0f / (1.0f + __expf(-pre));
                    if (g == 0) g_rh[(size_t)b * H + j] = sg * hloc[(jl << 5) + b];
                    else        zbuf[(jl << 5) + b] = sg;
                }
            }
            __syncthreads();
            if (tid == 0) arrive(&cnt_rh[R * 32]);
        }
        // ================= phase 2: n over r*h, state update ===========
        {
            waitge_warp(&cnt_rh[wid * 32], tgt);
            ull accA[JB], accB[JB];
#pragma unroll
            for (int v = 0; v < JB; v++) { accA[v] = 0ull; accB[v] = 0ull; }
            const float* hAp = g_rh + (size_t)bA * H + kbase;
            const float* hBp = g_rh + (size_t)bB * H + kbase;
            ulonglong2 a  = __ldcg((const ulonglong2*)hAp);
            ulonglong2 b2 = __ldcg((const ulonglong2*)hBp);
#pragma unroll
            for (int i = 0; i < ITERS; i++) {
                ulonglong2 ca = a, cb = b2;
                if (i + 1 < ITERS) {
                    a  = __ldcg((const ulonglong2*)(hAp + (i + 1) * 8));
                    b2 = __ldcg((const ulonglong2*)(hBp + (i + 1) * 8));
                }
                const float* wp = Ws2 + kbase + i * 8;
#pragma unroll
                for (int v = 0; v < JB; v++) {
                    ulonglong2 wv = *(const ulonglong2*)(wp + v * H);
                    accA[v] = fma2(ca.x, wv.x, accA[v]);
                    accA[v] = fma2(ca.y, wv.y, accA[v]);
                    accB[v] = fma2(cb.x, wv.x, accB[v]);
                    accB[v] = fma2(cb.y, wv.y, accB[v]);
                }
            }
#pragma unroll
            for (int v = 0; v < JB; v++) {
                ull oA = add2(accA[v], __shfl_xor_sync(0xffffffffu, accA[v], 16));
                ull oB = add2(accB[v], __shfl_xor_sync(0xffffffffu, accB[v], 16));
                red[(wid * JB + v) * 32 + lane] = (lane < 16) ? oA : oB;
            }
            __syncthreads();
#pragma unroll
            for (int pi = 0; pi < P2; pi++) {
                int o = tid + pi * NT;
                if (o < JB * 32) {
                    int jl = o >> 5, b = o & 31, j = j0 + jl;
                    ull s = red[jl * 32 + b];
#pragma unroll
                    for (int w = 1; w < 8; w++) s = add2(s, red[(w * JB + jl) * 32 + b]);
                    float2 p = unpk(s);
                    float dot = p.x + p.y;
                    float pre = x2[pi] + dot;
                    float n = tanhf(pre);
                    float z = zbuf[(jl << 5) + b];
                    float ho = hloc[(jl << 5) + b];
                    float hn = (1.0f - z) * ho + z * n;   // source convention
                    hloc[(jl << 5) + b] = hn;
                    g_h[(size_t)b * H + j] = hn;
                    y[((size_t)b * S_ + t) * H + j] = hn;
                }
            }
            __syncthreads();
            if (tid == 0) arrive(&cnt_h[R * 32]);
        }
    }
}

// reset flags so graph replays are deterministic
__global__ void reset_k() {
    int i = threadIdx.x + blockIdx.x * blockDim.x;
    if (i < 3 * 2 * 8 * 32) g_cnt[i] = 0u;
}

// ---------------- launch sequence ----------------
extern "C" void kernel_launch(void* const* d_in, const int* in_sizes, int n_in,
                              void* d_out, int out_size)
{
    const float* x   = (const float*)d_in[0];
    const float* Wi0 = (const float*)d_in[1];
    const float* Wh0 = (const float*)d_in[2];
    const float* bh0 = (const float*)d_in[3];
    const float* h00 = (const float*)d_in[4];
    const float* Wi1 = (const float*)d_in[5];
    const float* Wh1 = (const float*)d_in[6];
    const float* bh1 = (const float*)d_in[7];
    const float* h01 = (const float*)d_in[8];
    const float* Wi2 = (const float*)d_in[9];
    const float* Wh2 = (const float*)d_in[10];
    const float* bh2 = (const float*)d_in[11];
    const float* h02 = (const float*)d_in[12];
    const float* Wo  = (const float*)d_in[13];
    const float* bo  = (const float*)d_in[14];
    float* out = (float*)d_out;

    float *xg, *y0, *y1, *y2;
    cudaGetSymbolAddress((void**)&xg, g_xg);
    cudaGetSymbolAddress((void**)&y0, g_y0);
    cudaGetSymbolAddress((void**)&y1, g_y1);
    cudaGetSymbolAddress((void**)&y2, g_y2);

    // smem floats: Ws1(VR1*H) + Ws2(JB*H) + red(8*VR1*32 ull -> *2) + hloc + zbuf
    const int smem512  = (4 * 512  + 2 * 512  + 8 * 4 * 32 * 2 + 2 * 32 * 2) * 4;
    const int smem1024 = (8 * 1024 + 4 * 1024 + 8 * 8 * 32 * 2 + 4 * 32 * 2) * 4;
    cudaFuncSetAttribute(gru_scan<512, 2>,
                         cudaFuncAttributeMaxDynamicSharedMemorySize, smem512);
    cudaFuncSetAttribute(gru_scan<1024, 4>,
                         cudaFuncAttributeMaxDynamicSharedMemorySize, smem1024);

    dim3 thr(256);
    // layer 0
    gemm_k<<<dim3(1536 / 128, M_ / 128), thr>>>(x,  Wi0, bh0, xg, 1536, 256, 0);
    gru_scan<512, 2><<<NBSCAN, NT, smem512>>>(xg, Wh0, h00, y0, 0);
    // layer 1
    gemm_k<<<dim3(3072 / 128, M_ / 128), thr>>>(y0, Wi1, bh1, xg, 3072, 512, 0);
    gru_scan<1024, 4><<<NBSCAN, NT, smem1024>>>(xg, Wh1, h01, y1, 1);
    // layer 2
    gemm_k<<<dim3(1536 / 128, M_ / 128), thr>>>(y1, Wi2, bh2, xg, 1536, 1024, 0);
    gru_scan<512, 2><<<NBSCAN, NT, smem512>>>(xg, Wh2, h02, y2, 2);
    // output projection + relu
    gemm_k<<<dim3(256 / 128, M_ / 128), thr>>>(y2, Wo, bo, out, 256, 512, 1);
    // restore flag state for deterministic replay
    reset_k<<<4, 384>>>();
}

// round 14
// speedup vs baseline: 1.4719x; 1.4719x over previous
#include <cuda_runtime.h>
#include <math.h>

#define B_ 32
#define S_ 512
#define M_ (B_*S_)
#define NT 256
#define NBSCAN 128

typedef unsigned long long ull;

// ---------------- packed f32x2 helpers (Blackwell FFMA2 path) --------------
__device__ __forceinline__ ull fma2(ull a, ull b, ull c) {
    ull d;
    asm("fma.rn.f32x2 %0, %1, %2, %3;" : "=l"(d) : "l"(a), "l"(b), "l"(c));
    return d;
}
__device__ __forceinline__ ull add2(ull a, ull b) {
    ull d;
    asm("add.rn.f32x2 %0, %1, %2;" : "=l"(d) : "l"(a), "l"(b));
    return d;
}
__device__ __forceinline__ ull pack2(float x) {
    ull d;
    asm("mov.b64 %0, {%1, %1};" : "=l"(d) : "f"(x));
    return d;
}
__device__ __forceinline__ ull pk2(float lo, float hi) {
    ull d;
    asm("mov.b64 %0, {%1, %2};" : "=l"(d) : "f"(lo), "f"(hi));
    return d;
}
__device__ __forceinline__ float2 unpk(ull v) {
    float2 f;
    asm("mov.b64 {%0, %1}, %2;" : "=f"(f.x), "=f"(f.y) : "l"(v));
    return f;
}

// ---------------- device-global scratch (no allocations allowed) -----------
__device__ float g_xg[(size_t)M_ * 3072];
__device__ float g_y0[(size_t)M_ * 512];
__device__ float g_y1[(size_t)M_ * 1024];
__device__ float g_y2[(size_t)M_ * 512];
// TRANSPOSED hidden-state buffers: [k][batch], 32 floats (128B) per k-row.
__device__ float g_h [1024 * B_];
__device__ float g_rh[1024 * B_];
// region flags: [layer][phase:h/rh][region][pad32]  (zero-initialized)
__device__ unsigned g_cnt[3 * 2 * 8 * 32];

// lane-0-only acquire poll; short spin then tiny sleep.
__device__ __forceinline__ void waitge_warp(const unsigned* p, unsigned target) {
    if ((threadIdx.x & 31) == 0) {
        unsigned v;
        int spins = 0;
        for (;;) {
            asm volatile("ld.acquire.gpu.global.u32 %0, [%1];" : "=r"(v) : "l"(p) : "memory");
            if (v >= target) break;
            if (++spins > 32) __nanosleep(64);
        }
    }
    __syncwarp();
}
__device__ __forceinline__ void arrive(unsigned* p) {
    __threadfence();
    asm volatile("red.release.gpu.global.add.u32 [%0], 1;" :: "l"(p) : "memory");
}

// ---------------- GEMM: Y[M,N] = X[M,K] @ W[N,K]^T + bias, optional relu ---
// 128x128 tile, BK=8, 256 threads, 8x8 microtile, f32x2-packed accumulators.
__global__ void __launch_bounds__(256) gemm_k(
    const float* __restrict__ X, const float* __restrict__ W,
    const float* __restrict__ bias, float* __restrict__ Y,
    int N, int K, int relu)
{
    __shared__ float Xs[8][132];
    __shared__ float Wsm[8][132];
    const int tid = threadIdx.x;
    const int tx = tid & 15, ty = tid >> 4;
    const int n0 = blockIdx.x * 128, m0 = blockIdx.y * 128;
    const int lrow = tid >> 1;
    const int lkq  = (tid & 1) * 4;

    const float* Xp = X + (size_t)(m0 + lrow) * K + lkq;
    const float* Wp = W + (size_t)(n0 + lrow) * K + lkq;

    ull acc[8][4];
#pragma unroll
    for (int i = 0; i < 8; i++)
#pragma unroll
        for (int j = 0; j < 4; j++) acc[i][j] = 0ull;

    float4 xa = __ldg((const float4*)(Xp));
    float4 wa = __ldg((const float4*)(Wp));

    for (int kt = 0; kt < K; kt += 8) {
        __syncthreads();
        Xs[lkq + 0][lrow] = xa.x;  Xs[lkq + 1][lrow] = xa.y;
        Xs[lkq + 2][lrow] = xa.z;  Xs[lkq + 3][lrow] = xa.w;
        Wsm[lkq + 0][lrow] = wa.x; Wsm[lkq + 1][lrow] = wa.y;
        Wsm[lkq + 2][lrow] = wa.z; Wsm[lkq + 3][lrow] = wa.w;
        __syncthreads();
        if (kt + 8 < K) {
            xa = __ldg((const float4*)(Xp + kt + 8));
            wa = __ldg((const float4*)(Wp + kt + 8));
        }
#pragma unroll
        for (int k = 0; k < 8; k++) {
            float4 a0 = *(const float4*)&Xs[k][ty * 8];
            float4 a1 = *(const float4*)&Xs[k][ty * 8 + 4];
            ulonglong2 blo = *(const ulonglong2*)&Wsm[k][tx * 8];
            ulonglong2 bhi = *(const ulonglong2*)&Wsm[k][tx * 8 + 4];
            ull b0 = blo.x, b1 = blo.y, b2 = bhi.x, b3 = bhi.y;
            ull A;
            A = pack2(a0.x); acc[0][0]=fma2(A,b0,acc[0][0]); acc[0][1]=fma2(A,b1,acc[0][1]); acc[0][2]=fma2(A,b2,acc[0][2]); acc[0][3]=fma2(A,b3,acc[0][3]);
            A = pack2(a0.y); acc[1][0]=fma2(A,b0,acc[1][0]); acc[1][1]=fma2(A,b1,acc[1][1]); acc[1][2]=fma2(A,b2,acc[1][2]); acc[1][3]=fma2(A,b3,acc[1][3]);
            A = pack2(a0.z); acc[2][0]=fma2(A,b0,acc[2][0]); acc[2][1]=fma2(A,b1,acc[2][1]); acc[2][2]=fma2(A,b2,acc[2][2]); acc[2][3]=fma2(A,b3,acc[2][3]);
            A = pack2(a0.w); acc[3][0]=fma2(A,b0,acc[3][0]); acc[3][1]=fma2(A,b1,acc[3][1]); acc[3][2]=fma2(A,b2,acc[3][2]); acc[3][3]=fma2(A,b3,acc[3][3]);
            A = pack2(a1.x); acc[4][0]=fma2(A,b0,acc[4][0]); acc[4][1]=fma2(A,b1,acc[4][1]); acc[4][2]=fma2(A,b2,acc[4][2]); acc[4][3]=fma2(A,b3,acc[4][3]);
            A = pack2(a1.y); acc[5][0]=fma2(A,b0,acc[5][0]); acc[5][1]=fma2(A,b1,acc[5][1]); acc[5][2]=fma2(A,b2,acc[5][2]); acc[5][3]=fma2(A,b3,acc[5][3]);
            A = pack2(a1.z); acc[6][0]=fma2(A,b0,acc[6][0]); acc[6][1]=fma2(A,b1,acc[6][1]); acc[6][2]=fma2(A,b2,acc[6][2]); acc[6][3]=fma2(A,b3,acc[6][3]);
            A = pack2(a1.w); acc[7][0]=fma2(A,b0,acc[7][0]); acc[7][1]=fma2(A,b1,acc[7][1]); acc[7][2]=fma2(A,b2,acc[7][2]); acc[7][3]=fma2(A,b3,acc[7][3]);
        }
    }

    float bv[8];
    const float* bp = bias + n0 + tx * 8;
#pragma unroll
    for (int j = 0; j < 8; j++) bv[j] = __ldg(bp + j);

#pragma unroll
    for (int i = 0; i < 8; i++) {
        float* yp = Y + (size_t)(m0 + ty * 8 + i) * N + n0 + tx * 8;
#pragma unroll
        for (int j2 = 0; j2 < 4; j2++) {
            float2 p = unpk(acc[i][j2]);
            float o0 = p.x + bv[2 * j2];
            float o1 = p.y + bv[2 * j2 + 1];
            if (relu) { o0 = fmaxf(o0, 0.0f); o1 = fmaxf(o1, 0.0f); }
            float2 o; o.x = o0; o.y = o1;
            *(float2*)(yp + 2 * j2) = o;
        }
    }
}

// ---------------- persistent GRU scan (transposed state, lane=batch) -------
// 128 blocks (1 CTA/SM). Block owns JB hidden cols; warp w consumes k-region
// w (H/8 wide). lane = batch. g_h/g_rh are [k][32] so consumer LDGs are one
// 128B line per warp-instruction and producer stores are coalesced — this
// removes the 32-line L1tex wavefront storms of the [batch][H] layout.
// Producer blocks [16R,16R+16) own the cols of region R; per-region counters
// (target 16/step) give producer->consumer sync; lane-0-only polling.
template <int H, int JB>
__global__ void __launch_bounds__(NT) gru_scan(
    const float* __restrict__ xg, const float* __restrict__ Wh,
    const float* __restrict__ h0, float* __restrict__ y, int L)
{
    constexpr int VR1 = 2 * JB;          // phase-1 rows (r,z interleaved)
    constexpr int G3  = 3 * H;
    constexpr int KW  = H / 8;           // k per warp region
    constexpr int ITQ = KW / 4;          // 4-k quads per warp
    constexpr int P1  = (VR1 * 32 + NT - 1) / NT;
    constexpr int P2  = (JB * 32 + NT - 1) / NT;

    extern __shared__ float smem[];
    float* Ws1  = smem;                          // VR1*H   r/z rows (v=2*jl+g)
    float* Ws2  = Ws1 + VR1 * H;                 // JB*H    n rows
    ull*   red  = (ull*)(Ws2 + JB * H);          // 8*VR1*32 partials
    float* hloc = (float*)(red + 8 * VR1 * 32);  // JB*32
    float* zbuf = hloc + JB * 32;                // JB*32

    const int tid  = threadIdx.x;
    const int wid  = tid >> 5;
    const int lane = tid & 31;           // lane == batch
    const int j0   = blockIdx.x * JB;
    const int R    = blockIdx.x >> 4;    // my producer region

    unsigned* cnt_h  = g_cnt + ((L * 2 + 0) * 8) * 32;
    unsigned* cnt_rh = g_cnt + ((L * 2 + 1) * 8) * 32;

    // cache Wh slice in shared (reused 512 steps)
    for (int i = tid; i < VR1 * H; i += NT) {
        int v = i / H, k = i - v * H;
        int jl = v >> 1, g = v & 1;
        Ws1[i] = Wh[(size_t)(g * H + j0 + jl) * H + k];
    }
    for (int i = tid; i < JB * H; i += NT) {
        int jl = i / H, k = i - jl * H;
        Ws2[i] = Wh[(size_t)(2 * H + j0 + jl) * H + k];
    }
    // init hidden state (h0 broadcast over batch), transposed [k][b]
    for (int i = tid; i < JB * 32; i += NT) {
        int jl = i >> 5, b = i & 31;
        float v = h0[j0 + jl];
        hloc[i] = v;
        g_h[(size_t)(j0 + jl) * 32 + b] = v;
    }
    __syncthreads();
    if (tid == 0) arrive(&cnt_h[R * 32]);

    const int kbase = wid * KW;

    for (int t = 0; t < S_; t++) {
        const unsigned tgt = 16u * (unsigned)(t + 1);

        // -------- prefetch this step's xg values (independent of flags) ----
        float x1[P1];
#pragma unroll
        for (int pi = 0; pi < P1; pi++) {
            int o = tid + pi * NT;
            if (o < VR1 * 32) {
                int v = o >> 5, b = o & 31;
                int jl = v >> 1, g = v & 1;
                x1[pi] = __ldg(&xg[((size_t)b * S_ + t) * G3 + g * H + j0 + jl]);
            }
        }
        float x2[P2];
#pragma unroll
        for (int pi = 0; pi < P2; pi++) {
            int o = tid + pi * NT;
            if (o < JB * 32) {
                int jl = o >> 5, b = o & 31;
                x2[pi] = __ldg(&xg[((size_t)b * S_ + t) * G3 + 2 * H + j0 + jl]);
            }
        }

        // ================= phase 1: r,z over h =================
        {
            waitge_warp(&cnt_h[wid * 32], tgt);
            ull acc[VR1];
#pragma unroll
            for (int v = 0; v < VR1; v++) acc[v] = 0ull;
            const float* hp = g_h + (size_t)kbase * 32 + lane;
#pragma unroll 4
            for (int q = 0; q < ITQ; q++) {
                float h0v = __ldcg(hp + (q * 4 + 0) * 32);
                float h1v = __ldcg(hp + (q * 4 + 1) * 32);
                float h2v = __ldcg(hp + (q * 4 + 2) * 32);
                float h3v = __ldcg(hp + (q * 4 + 3) * 32);
                ull hp01 = pk2(h0v, h1v), hp23 = pk2(h2v, h3v);
                const float* wp = Ws1 + kbase + q * 4;
#pragma unroll
                for (int v = 0; v < VR1; v++) {
                    ulonglong2 wv = *(const ulonglong2*)(wp + v * H);
                    acc[v] = fma2(hp01, wv.x, acc[v]);
                    acc[v] = fma2(hp23, wv.y, acc[v]);
                }
            }
#pragma unroll
            for (int v = 0; v < VR1; v++)
                red[(wid * VR1 + v) * 32 + lane] = acc[v];
            __syncthreads();
#pragma unroll
            for (int pi = 0; pi < P1; pi++) {
                int o = tid + pi * NT;
                if (o < VR1 * 32) {
                    int v = o >> 5, b = o & 31;
                    ull s = red[v * 32 + b];
#pragma unroll
                    for (int w = 1; w < 8; w++) s = add2(s, red[(w * VR1 + v) * 32 + b]);
                    float2 p = unpk(s);
                    float dot = p.x + p.y;
                    int jl = v >> 1, g = v & 1, j = j0 + jl;
                    float pre = x1[pi] + dot;
                    float sg = 1.0f / (1.0f + __expf(-pre));
                    if (g == 0) g_rh[(size_t)j * 32 + b] = sg * hloc[(jl << 5) + b];
                    else        zbuf[(jl << 5) + b] = sg;
                }
            }
            __syncthreads();
            if (tid == 0) arrive(&cnt_rh[R * 32]);
        }
        // ================= phase 2: n over r*h, state update ===========
        {
            waitge_warp(&cnt_rh[wid * 32], tgt);
            ull acc[JB];
#pragma unroll
            for (int v = 0; v < JB; v++) acc[v] = 0ull;
            const float* hp = g_rh + (size_t)kbase * 32 + lane;
#pragma unroll 4
            for (int q = 0; q < ITQ; q++) {
                float h0v = __ldcg(hp + (q * 4 + 0) * 32);
                float h1v = __ldcg(hp + (q * 4 + 1) * 32);
                float h2v = __ldcg(hp + (q * 4 + 2) * 32);
                float h3v = __ldcg(hp + (q * 4 + 3) * 32);
                ull hp01 = pk2(h0v, h1v), hp23 = pk2(h2v, h3v);
                const float* wp = Ws2 + kbase + q * 4;
#pragma unroll
                for (int v = 0; v < JB; v++) {
                    ulonglong2 wv = *(const ulonglong2*)(wp + v * H);
                    acc[v] = fma2(hp01, wv.x, acc[v]);
                    acc[v] = fma2(hp23, wv.y, acc[v]);
                }
            }
#pragma unroll
            for (int v = 0; v < JB; v++)
                red[(wid * JB + v) * 32 + lane] = acc[v];
            __syncthreads();
#pragma unroll
            for (int pi = 0; pi < P2; pi++) {
                int o = tid + pi * NT;
                if (o < JB * 32) {
                    int jl = o >> 5, b = o & 31, j = j0 + jl;
                    ull s = red[jl * 32 + b];
#pragma unroll
                    for (int w = 1; w < 8; w++) s = add2(s, red[(w * JB + jl) * 32 + b]);
                    float2 p = unpk(s);
                    float dot = p.x + p.y;
                    float pre = x2[pi] + dot;
                    float n = tanhf(pre);
                    float z = zbuf[(jl << 5) + b];
                    float ho = hloc[(jl << 5) + b];
                    float hn = (1.0f - z) * ho + z * n;   // source convention
                    hloc[(jl << 5) + b] = hn;
                    g_h[(size_t)j * 32 + b] = hn;
                    y[((size_t)b * S_ + t) * H + j] = hn;
                }
            }
            __syncthreads();
            if (tid == 0) arrive(&cnt_h[R * 32]);
        }
    }
}

// reset flags so graph replays are deterministic
__global__ void reset_k() {
    int i = threadIdx.x + blockIdx.x * blockDim.x;
    if (i < 3 * 2 * 8 * 32) g_cnt[i] = 0u;
}

// ---------------- launch sequence ----------------
extern "C" void kernel_launch(void* const* d_in, const int* in_sizes, int n_in,
                              void* d_out, int out_size)
{
    const float* x   = (const float*)d_in[0];
    const float* Wi0 = (const float*)d_in[1];
    const float* Wh0 = (const float*)d_in[2];
    const float* bh0 = (const float*)d_in[3];
    const float* h00 = (const float*)d_in[4];
    const float* Wi1 = (const float*)d_in[5];
    const float* Wh1 = (const float*)d_in[6];
    const float* bh1 = (const float*)d_in[7];
    const float* h01 = (const float*)d_in[8];
    const float* Wi2 = (const float*)d_in[9];
    const float* Wh2 = (const float*)d_in[10];
    const float* bh2 = (const float*)d_in[11];
    const float* h02 = (const float*)d_in[12];
    const float* Wo  = (const float*)d_in[13];
    const float* bo  = (const float*)d_in[14];
    float* out = (float*)d_out;

    float *xg, *y0, *y1, *y2;
    cudaGetSymbolAddress((void**)&xg, g_xg);
    cudaGetSymbolAddress((void**)&y0, g_y0);
    cudaGetSymbolAddress((void**)&y1, g_y1);
    cudaGetSymbolAddress((void**)&y2, g_y2);

    // smem floats: Ws1(VR1*H) + Ws2(JB*H) + red(8*VR1*32 ull) + hloc + zbuf
    const int smem512  = (8 * 512   + 4 * 512  + 8 * 8 * 32 * 2  + 4 * 32 * 2) * 4;
    const int smem1024 = (16 * 1024 + 8 * 1024 + 8 * 16 * 32 * 2 + 8 * 32 * 2) * 4;
    cudaFuncSetAttribute(gru_scan<512, 4>,
                         cudaFuncAttributeMaxDynamicSharedMemorySize, smem512);
    cudaFuncSetAttribute(gru_scan<1024, 8>,
                         cudaFuncAttributeMaxDynamicSharedMemorySize, smem1024);

    dim3 thr(256);
    // layer 0
    gemm_k<<<dim3(1536 / 128, M_ / 128), thr>>>(x,  Wi0, bh0, xg, 1536, 256, 0);
    gru_scan<512, 4><<<NBSCAN, NT, smem512>>>(xg, Wh0, h00, y0, 0);
    // layer 1
    gemm_k<<<dim3(3072 / 128, M_ / 128), thr>>>(y0, Wi1, bh1, xg, 3072, 512, 0);
    gru_scan<1024, 8><<<NBSCAN, NT, smem1024>>>(xg, Wh1, h01, y1, 1);
    // layer 2
    gemm_k<<<dim3(1536 / 128, M_ / 128), thr>>>(y1, Wi2, bh2, xg, 1536, 1024, 0);
    gru_scan<512, 4><<<NBSCAN, NT, smem512>>>(xg, Wh2, h02, y2, 2);
    // output projection + relu
    gemm_k<<<dim3(256 / 128, M_ / 128), thr>>>(y2, Wo, bo, out, 256, 512, 1);
    // restore flag state for deterministic replay
    reset_k<<<4, 384>>>();
}